// round 1
// baseline (speedup 1.0000x reference)
#include <cuda_runtime.h>
#include <cuda_bf16.h>
#include <math.h>

// ---------------- problem constants ----------------
#define NN      50000
#define EE      800000
#define TOTE    (EE + NN)      // 850000 edges incl self loops
#define FIN     256
#define HH      4
#define CC      128
#define HC      (HH * CC)      // 512
#define VV      3

// ---------------- device scratch (globals; no cudaMalloc allowed) ----------
__device__ float g_h[(size_t)NN * HC];            // 102.4 MB  (per-view, reused)
__device__ float g_views[(size_t)VV * NN * CC];   // 76.8 MB
__device__ float g_ssrc[NN * HH];
__device__ float g_sdst[NN * HH];
__device__ float g_m[NN * HH];
__device__ float g_denom[NN * HH];
__device__ int   g_count[NN];
__device__ int   g_cursor[NN];
__device__ int   g_indptr[NN + 1];
__device__ int   g_csrc[TOTE];
__device__ float g_cex[(size_t)TOTE * HH];        // 13.6 MB

// ---------------- helpers ----------------
__device__ __forceinline__ void atomicMaxFloat(float* addr, float value) {
    if (value >= 0.0f)
        atomicMax((int*)addr, __float_as_int(value));
    else
        atomicMin((unsigned int*)addr, __float_as_uint(value));
}

// ---------------- 1) SGEMM: g_h = x[N,256] @ W[256,512] ----------------
// classic 128x128x8 tiled fp32 gemm, 256 threads, 8x8 microtile
__global__ void sgemm_kernel(const float* __restrict__ A,
                             const float* __restrict__ B,
                             int M, int N, int K) {
    const int BM = 128, BN = 128, BK = 8, TM = 8, TN = 8;
    __shared__ float As[BK][BM];
    __shared__ float Bs[BK][BN];

    int bx = blockIdx.x;             // N tiles
    int by = blockIdx.y;             // M tiles
    int tid = threadIdx.x;           // 256
    int tx = tid % 16, ty = tid / 16;

    int aRow = tid >> 1;             // 0..127
    int aCol = (tid & 1) * 4;        // 0 or 4
    int bRow = tid >> 5;             // 0..7
    int bCol = (tid & 31) * 4;       // 0..124

    int mbase = by * BM;
    const float* Ablk = A + (size_t)mbase * K;
    const float* Bblk = B + bx * BN;

    float acc[TM][TN];
#pragma unroll
    for (int i = 0; i < TM; i++)
#pragma unroll
        for (int j = 0; j < TN; j++) acc[i][j] = 0.0f;

    for (int k0 = 0; k0 < K; k0 += BK) {
        float4 av = make_float4(0.f, 0.f, 0.f, 0.f);
        if (mbase + aRow < M)
            av = *(const float4*)&Ablk[(size_t)aRow * K + k0 + aCol];
        As[aCol + 0][aRow] = av.x;
        As[aCol + 1][aRow] = av.y;
        As[aCol + 2][aRow] = av.z;
        As[aCol + 3][aRow] = av.w;

        float4 bv = *(const float4*)&Bblk[(size_t)(k0 + bRow) * N + bCol];
        *(float4*)&Bs[bRow][bCol] = bv;
        __syncthreads();

#pragma unroll
        for (int kk = 0; kk < BK; kk++) {
            float ar[TM], br[TN];
#pragma unroll
            for (int i = 0; i < TM; i++) ar[i] = As[kk][ty * TM + i];
#pragma unroll
            for (int j = 0; j < TN; j++) br[j] = Bs[kk][tx * TN + j];
#pragma unroll
            for (int i = 0; i < TM; i++)
#pragma unroll
                for (int j = 0; j < TN; j++) acc[i][j] += ar[i] * br[j];
        }
        __syncthreads();
    }

#pragma unroll
    for (int i = 0; i < TM; i++) {
        int row = mbase + ty * TM + i;
        if (row < M) {
#pragma unroll
            for (int j = 0; j < TN; j += 4) {
                *(float4*)&g_h[(size_t)row * N + bx * BN + tx * TN + j] =
                    make_float4(acc[i][j], acc[i][j + 1], acc[i][j + 2], acc[i][j + 3]);
            }
        }
    }
}

// ---------------- 2) attention scalar scores per node ----------------
// one warp per node: s_src[n,h] = sum_c h[n,h,c]*a_src[h,c]   (and s_dst)
__global__ void s_kernel(const float* __restrict__ asrc,
                         const float* __restrict__ adst) {
    int gw = (blockIdx.x * blockDim.x + threadIdx.x) >> 5;
    int lane = threadIdx.x & 31;
    if (gw >= NN) return;
    const float* hr = g_h + (size_t)gw * HC;
    float ps[HH] = {0.f, 0.f, 0.f, 0.f};
    float pd[HH] = {0.f, 0.f, 0.f, 0.f};
#pragma unroll
    for (int c0 = 0; c0 < HC; c0 += 32) {
        int ch = c0 + lane;
        int hd = ch >> 7;   // constant within the 32-chunk
        float v = hr[ch];
        ps[hd] += v * asrc[ch];
        pd[hd] += v * adst[ch];
    }
#pragma unroll
    for (int hd = 0; hd < HH; hd++) {
        float a = ps[hd], d = pd[hd];
#pragma unroll
        for (int off = 16; off; off >>= 1) {
            a += __shfl_xor_sync(0xFFFFFFFFu, a, off);
            d += __shfl_xor_sync(0xFFFFFFFFu, d, off);
        }
        if (lane == 0) {
            g_ssrc[gw * HH + hd] = a;
            g_sdst[gw * HH + hd] = d;
        }
    }
}

// ---------------- per-view init ----------------
__global__ void init_kernel() {
    int i = blockIdx.x * blockDim.x + threadIdx.x;
    if (i < NN * HH) {
        g_m[i] = -INFINITY;
        g_denom[i] = 0.0f;
    }
    if (i < NN) g_count[i] = 0;
}

// ---------------- 3) edge pass 1: segment max + degree histogram ----------
__global__ void edge_pass1(const int* __restrict__ ei) {
    int e = blockIdx.x * blockDim.x + threadIdx.x;
    if (e >= TOTE) return;
    int src, dst;
    if (e < EE) { src = ei[e]; dst = ei[EE + e]; }
    else        { src = dst = e - EE; }
#pragma unroll
    for (int hd = 0; hd < HH; hd++) {
        float sc = g_ssrc[src * HH + hd] + g_sdst[dst * HH + hd];
        sc = (sc > 0.f) ? sc : 0.2f * sc;
        atomicMaxFloat(&g_m[dst * HH + hd], sc);
    }
    atomicAdd(&g_count[dst], 1);
}

// ---------------- 4) exclusive scan of counts -> indptr / cursor ----------
__global__ void scan_kernel() {
    __shared__ int sdata[1024];
    __shared__ int s_carry;
    int tid = threadIdx.x;
    if (tid == 0) s_carry = 0;
    __syncthreads();
    for (int base = 0; base < NN; base += 1024) {
        int i = base + tid;
        int v = (i < NN) ? g_count[i] : 0;
        sdata[tid] = v;
        __syncthreads();
#pragma unroll
        for (int off = 1; off < 1024; off <<= 1) {
            int t = (tid >= off) ? sdata[tid - off] : 0;
            __syncthreads();
            sdata[tid] += t;
            __syncthreads();
        }
        int excl = sdata[tid] - v + s_carry;
        if (i < NN) { g_indptr[i] = excl; g_cursor[i] = excl; }
        int tot = sdata[1023];
        __syncthreads();
        if (tid == 0) s_carry += tot;
        __syncthreads();
    }
    if (tid == 0) g_indptr[NN] = s_carry;
}

// ---------------- 5) edge pass 2: exp, denom, CSR scatter ----------------
__global__ void edge_pass2(const int* __restrict__ ei) {
    int e = blockIdx.x * blockDim.x + threadIdx.x;
    if (e >= TOTE) return;
    int src, dst;
    if (e < EE) { src = ei[e]; dst = ei[EE + e]; }
    else        { src = dst = e - EE; }
    float ex[HH];
#pragma unroll
    for (int hd = 0; hd < HH; hd++) {
        float sc = g_ssrc[src * HH + hd] + g_sdst[dst * HH + hd];
        sc = (sc > 0.f) ? sc : 0.2f * sc;
        ex[hd] = __expf(sc - g_m[dst * HH + hd]);
        atomicAdd(&g_denom[dst * HH + hd], ex[hd]);
    }
    int idx = atomicAdd(&g_cursor[dst], 1);
    g_csrc[idx] = src;
    *(float4*)&g_cex[(size_t)idx * 4] = make_float4(ex[0], ex[1], ex[2], ex[3]);
}

// ---------------- 6) CSR gather aggregation + head-mean + bias + ELU -----
// block of 128 threads per destination node; thread t owns channels 4t..4t+3
__global__ void aggregate_kernel(const float* __restrict__ bias, int view) {
    int dst = blockIdx.x;
    int tid = threadIdx.x;           // 0..127
    int head = tid >> 5;             // channels 4t..4t+3 all in this head
    float4 acc = make_float4(0.f, 0.f, 0.f, 0.f);
    int beg = g_indptr[dst], end = g_indptr[dst + 1];
    for (int i = beg; i < end; i++) {
        int src = g_csrc[i];
        float ex = g_cex[(size_t)i * 4 + head];
        float4 hv = *(const float4*)&g_h[(size_t)src * HC + tid * 4];
        acc.x += ex * hv.x;
        acc.y += ex * hv.y;
        acc.z += ex * hv.z;
        acc.w += ex * hv.w;
    }
    float d = g_denom[dst * HH + head];
    float inv = 1.0f / fmaxf(d, 1e-16f);
    __shared__ float s[HC];
    s[tid * 4 + 0] = acc.x * inv;
    s[tid * 4 + 1] = acc.y * inv;
    s[tid * 4 + 2] = acc.z * inv;
    s[tid * 4 + 3] = acc.w * inv;
    __syncthreads();
    float v = 0.25f * (s[tid] + s[tid + 128] + s[tid + 256] + s[tid + 384]) + bias[tid];
    v = (v > 0.f) ? v : expm1f(v);
    g_views[(size_t)view * NN * CC + (size_t)dst * CC + tid] = v;
}

// ---------------- 7) fusion (view attention) + classifier ----------------
__global__ void fusion_kernel(const float* __restrict__ fw,
                              const float* __restrict__ fb,
                              const float* __restrict__ w1,
                              const float* __restrict__ b1,
                              const float* __restrict__ w2,
                              const float* __restrict__ b2,
                              float* __restrict__ out_logits,
                              float* __restrict__ out_w,
                              int npb, int write_w) {
    __shared__ float w1s[CC * 64];   // [128,64] row-major
    __shared__ float fws[CC];
    __shared__ float w2s[128];       // [64,2]
    __shared__ float red[12];
    __shared__ float sw[3];
    __shared__ float fused_s[CC];
    __shared__ float hcls_s[64];

    int tid = threadIdx.x;           // 128
    for (int i = tid; i < CC * 64; i += 128) w1s[i] = w1[i];
    fws[tid] = fw[tid];
    w2s[tid] = w2[tid];
    __syncthreads();

    const size_t NSTR = (size_t)NN * CC;
    int start = blockIdx.x * npb;
    int endn = min(NN, start + npb);
    int lane = tid & 31, wrp = tid >> 5;

    for (int node = start; node < endn; node++) {
        float v0 = g_views[(size_t)node * CC + tid];
        float v1 = g_views[NSTR + (size_t)node * CC + tid];
        float v2 = g_views[2 * NSTR + (size_t)node * CC + tid];
        float f = fws[tid];
        float p0 = v0 * f, p1 = v1 * f, p2 = v2 * f;
#pragma unroll
        for (int off = 16; off; off >>= 1) {
            p0 += __shfl_xor_sync(0xFFFFFFFFu, p0, off);
            p1 += __shfl_xor_sync(0xFFFFFFFFu, p1, off);
            p2 += __shfl_xor_sync(0xFFFFFFFFu, p2, off);
        }
        if (lane == 0) { red[wrp] = p0; red[4 + wrp] = p1; red[8 + wrp] = p2; }
        __syncthreads();
        if (tid == 0) {
            float s0 = red[0] + red[1] + red[2] + red[3] + fb[0];
            float s1 = red[4] + red[5] + red[6] + red[7] + fb[0];
            float s2 = red[8] + red[9] + red[10] + red[11] + fb[0];
            float mx = fmaxf(s0, fmaxf(s1, s2));
            float e0 = expf(s0 - mx), e1 = expf(s1 - mx), e2 = expf(s2 - mx);
            float inv = 1.0f / (e0 + e1 + e2);
            sw[0] = e0 * inv; sw[1] = e1 * inv; sw[2] = e2 * inv;
            if (write_w) {
                out_w[node * 3 + 0] = sw[0];
                out_w[node * 3 + 1] = sw[1];
                out_w[node * 3 + 2] = sw[2];
            }
        }
        __syncthreads();
        fused_s[tid] = sw[0] * v0 + sw[1] * v1 + sw[2] * v2;
        __syncthreads();
        if (tid < 64) {
            float a = b1[tid];
#pragma unroll 8
            for (int c = 0; c < CC; c++) a += fused_s[c] * w1s[c * 64 + tid];
            hcls_s[tid] = fmaxf(a, 0.f);
        }
        __syncthreads();
        if (tid < 2) {
            float a = b2[tid];
#pragma unroll 8
            for (int k = 0; k < 64; k++) a += hcls_s[k] * w2s[k * 2 + tid];
            out_logits[node * 2 + tid] = a;
        }
        __syncthreads();
    }
}

// ---------------- launcher ----------------
extern "C" void kernel_launch(void* const* d_in, const int* in_sizes, int n_in,
                              void* d_out, int out_size) {
    const float* x     = (const float*)d_in[0];
    const int*   ei0   = (const int*)d_in[1];
    const int*   ei1   = (const int*)d_in[2];
    const int*   ei2   = (const int*)d_in[3];
    const float* W     = (const float*)d_in[4];
    const float* a_src = (const float*)d_in[5];
    const float* a_dst = (const float*)d_in[6];
    const float* b     = (const float*)d_in[7];
    const float* fus_w = (const float*)d_in[8];
    const float* fus_b = (const float*)d_in[9];
    const float* w1    = (const float*)d_in[10];
    const float* b1    = (const float*)d_in[11];
    const float* w2    = (const float*)d_in[12];
    const float* b2    = (const float*)d_in[13];
    float* out = (float*)d_out;

    const int* eis[VV] = { ei0, ei1, ei2 };

    dim3 gemm_grid(HC / 128, (NN + 127) / 128);
    int sgrid   = (NN * 32 + 255) / 256;
    int igrid   = (NN * HH + 255) / 256;
    int egrid   = (TOTE + 255) / 256;

    for (int v = 0; v < VV; v++) {
        sgemm_kernel<<<gemm_grid, 256>>>(x, W + (size_t)v * FIN * HC, NN, HC, FIN);
        s_kernel<<<sgrid, 256>>>(a_src + v * HC, a_dst + v * HC);
        init_kernel<<<igrid, 256>>>();
        edge_pass1<<<egrid, 256>>>(eis[v]);
        scan_kernel<<<1, 1024>>>();
        edge_pass2<<<egrid, 256>>>(eis[v]);
        aggregate_kernel<<<NN, 128>>>(b + v * CC, v);
    }

    int write_w = (out_size >= NN * 2 + NN * 3) ? 1 : 0;
    int nblocks = 500;
    int npb = (NN + nblocks - 1) / nblocks;
    fusion_kernel<<<nblocks, 128>>>(fus_w, fus_b, w1, b1, w2, b2,
                                    out, out + NN * 2, npb, write_w);
}

// round 2
// speedup vs baseline: 2.5327x; 2.5327x over previous
#include <cuda_runtime.h>
#include <cuda_bf16.h>
#include <math.h>
#include <stdint.h>

// ---------------- problem constants ----------------
#define NN      50000
#define EE      800000
#define TOTE    (EE + NN)      // 850000 edges incl self loops
#define FIN     256
#define HH      4
#define CC      128
#define HC      (HH * CC)      // 512
#define VV      3
#define GN      (VV * HC)      // 1536 fused output cols

// ---------------- device scratch (globals; no cudaMalloc allowed) ----------
__device__ float g_h[(size_t)VV * NN * HC];       // 307 MB (all views)
__device__ float g_views[(size_t)VV * NN * CC];   // 76.8 MB
__device__ float g_ssrc[NN * HH];
__device__ float g_sdst[NN * HH];
__device__ float g_m[NN * HH];
__device__ float g_denom[NN * HH];
__device__ int   g_count[NN];
__device__ int   g_cursor[NN];
__device__ int   g_indptr[NN + 1];
__device__ int   g_btot[64];
__device__ int   g_boff[64];
__device__ int   g_csrc[TOTE];
__device__ float g_cex[(size_t)TOTE * HH];        // 13.6 MB

// ---------------- helpers ----------------
__device__ __forceinline__ void atomicMaxFloat(float* addr, float value) {
    if (value >= 0.0f)
        atomicMax((int*)addr, __float_as_int(value));
    else
        atomicMin((unsigned int*)addr, __float_as_uint(value));
}

__device__ __forceinline__ uint32_t f2tf(float f) {
    uint32_t u;
    asm("cvt.rna.tf32.f32 %0, %1;" : "=r"(u) : "f"(f));
    return u;
}

__device__ __forceinline__ void mma_tf32(float& c0, float& c1, float& c2, float& c3,
                                         uint32_t a0, uint32_t a1, uint32_t a2, uint32_t a3,
                                         uint32_t b0, uint32_t b1) {
    asm volatile(
        "mma.sync.aligned.m16n8k8.row.col.f32.tf32.tf32.f32 "
        "{%0,%1,%2,%3}, {%4,%5,%6,%7}, {%8,%9}, {%0,%1,%2,%3};"
        : "+f"(c0), "+f"(c1), "+f"(c2), "+f"(c3)
        : "r"(a0), "r"(a1), "r"(a2), "r"(a3), "r"(b0), "r"(b1));
}

// ---------------- 1) TF32 MMA GEMM: g_h = x[N,256] @ W[v][256,512], all views
// BM=128 BN=128 BK=32, 256 threads = 8 warps (2m x 4n), warp tile 64x32
#define AKP 36
#define BNP 136
__global__ void gemm_tf32_kernel(const float* __restrict__ A,
                                 const float* __restrict__ W) {
    __shared__ uint32_t As[128 * AKP];   // 18.4 KB
    __shared__ uint32_t Bs[32 * BNP];    // 17.4 KB

    int tid = threadIdx.x;
    int warp = tid >> 5, lane = tid & 31;
    int wm = warp >> 2;          // 0..1
    int wn = warp & 3;           // 0..3
    int grp = lane >> 2, qid = lane & 3;

    int mbase = blockIdx.y * 128;
    int nbase = blockIdx.x * 128;
    int v = nbase >> 9;
    int nc0 = nbase & 511;
    const float* Bp = W + (size_t)v * FIN * HC + nc0;   // row stride HC

    float acc[4][4][4];
#pragma unroll
    for (int mi = 0; mi < 4; mi++)
#pragma unroll
        for (int ni = 0; ni < 4; ni++)
#pragma unroll
            for (int r = 0; r < 4; r++) acc[mi][ni][r] = 0.0f;

    for (int k0 = 0; k0 < FIN; k0 += 32) {
        // A tile: 128 x 32 -> 1024 float4, 4 per thread
#pragma unroll
        for (int i = 0; i < 4; i++) {
            int idx = tid + i * 256;
            int r = idx >> 3;
            int c4 = (idx & 7) * 4;
            float4 av = make_float4(0.f, 0.f, 0.f, 0.f);
            if (mbase + r < NN)
                av = *(const float4*)&A[(size_t)(mbase + r) * FIN + k0 + c4];
            uint32_t* dst = &As[r * AKP + c4];
            dst[0] = f2tf(av.x); dst[1] = f2tf(av.y);
            dst[2] = f2tf(av.z); dst[3] = f2tf(av.w);
        }
        // B tile: 32 x 128
#pragma unroll
        for (int i = 0; i < 4; i++) {
            int idx = tid + i * 256;
            int r = idx >> 5;
            int c4 = (idx & 31) * 4;
            float4 bv = *(const float4*)&Bp[(size_t)(k0 + r) * HC + c4];
            uint32_t* dst = &Bs[r * BNP + c4];
            dst[0] = f2tf(bv.x); dst[1] = f2tf(bv.y);
            dst[2] = f2tf(bv.z); dst[3] = f2tf(bv.w);
        }
        __syncthreads();

#pragma unroll
        for (int kk = 0; kk < 4; kk++) {
            int ko = kk * 8;
            uint32_t af[4][4];
#pragma unroll
            for (int mi = 0; mi < 4; mi++) {
                int rb = wm * 64 + mi * 16;
                af[mi][0] = As[(rb + grp) * AKP + ko + qid];
                af[mi][1] = As[(rb + 8 + grp) * AKP + ko + qid];
                af[mi][2] = As[(rb + grp) * AKP + ko + 4 + qid];
                af[mi][3] = As[(rb + 8 + grp) * AKP + ko + 4 + qid];
            }
            uint32_t bf[4][2];
#pragma unroll
            for (int ni = 0; ni < 4; ni++) {
                int cb = wn * 32 + ni * 8 + grp;
                bf[ni][0] = Bs[(ko + qid) * BNP + cb];
                bf[ni][1] = Bs[(ko + 4 + qid) * BNP + cb];
            }
#pragma unroll
            for (int mi = 0; mi < 4; mi++)
#pragma unroll
                for (int ni = 0; ni < 4; ni++)
                    mma_tf32(acc[mi][ni][0], acc[mi][ni][1], acc[mi][ni][2], acc[mi][ni][3],
                             af[mi][0], af[mi][1], af[mi][2], af[mi][3],
                             bf[ni][0], bf[ni][1]);
        }
        __syncthreads();
    }

    // epilogue
    float* hbase = g_h + (size_t)v * NN * HC;
#pragma unroll
    for (int mi = 0; mi < 4; mi++) {
#pragma unroll
        for (int ni = 0; ni < 4; ni++) {
            int nc = nc0 + wn * 32 + ni * 8 + qid * 2;
            int r0 = mbase + wm * 64 + mi * 16 + grp;
            if (r0 < NN)
                *(float2*)&hbase[(size_t)r0 * HC + nc] =
                    make_float2(acc[mi][ni][0], acc[mi][ni][1]);
            int r1 = r0 + 8;
            if (r1 < NN)
                *(float2*)&hbase[(size_t)r1 * HC + nc] =
                    make_float2(acc[mi][ni][2], acc[mi][ni][3]);
        }
    }
}

// ---------------- 2) attention scalar scores per node ----------------
__global__ void s_kernel(const float* __restrict__ h,
                         const float* __restrict__ asrc,
                         const float* __restrict__ adst) {
    int gw = (blockIdx.x * blockDim.x + threadIdx.x) >> 5;
    int lane = threadIdx.x & 31;
    if (gw >= NN) return;
    const float* hr = h + (size_t)gw * HC;
    float ps[HH] = {0.f, 0.f, 0.f, 0.f};
    float pd[HH] = {0.f, 0.f, 0.f, 0.f};
#pragma unroll
    for (int c0 = 0; c0 < HC; c0 += 32) {
        int ch = c0 + lane;
        int hd = ch >> 7;
        float v = hr[ch];
        ps[hd] += v * asrc[ch];
        pd[hd] += v * adst[ch];
    }
#pragma unroll
    for (int hd = 0; hd < HH; hd++) {
        float a = ps[hd], d = pd[hd];
#pragma unroll
        for (int off = 16; off; off >>= 1) {
            a += __shfl_xor_sync(0xFFFFFFFFu, a, off);
            d += __shfl_xor_sync(0xFFFFFFFFu, d, off);
        }
        if (lane == 0) {
            g_ssrc[gw * HH + hd] = a;
            g_sdst[gw * HH + hd] = d;
        }
    }
}

// ---------------- per-view init ----------------
__global__ void init_kernel() {
    int i = blockIdx.x * blockDim.x + threadIdx.x;
    if (i < NN * HH) {
        g_m[i] = -INFINITY;
        g_denom[i] = 0.0f;
    }
    if (i < NN) g_count[i] = 0;
}

// ---------------- 3) edge pass 1: segment max + degree histogram ----------
__global__ void edge_pass1(const int* __restrict__ ei) {
    int e = blockIdx.x * blockDim.x + threadIdx.x;
    if (e >= TOTE) return;
    int src, dst;
    if (e < EE) { src = ei[e]; dst = ei[EE + e]; }
    else        { src = dst = e - EE; }
    float4 s4 = *(const float4*)&g_ssrc[src * HH];
    float4 d4 = *(const float4*)&g_sdst[dst * HH];
    float sc[HH] = { s4.x + d4.x, s4.y + d4.y, s4.z + d4.z, s4.w + d4.w };
#pragma unroll
    for (int hd = 0; hd < HH; hd++) {
        float s = sc[hd];
        s = (s > 0.f) ? s : 0.2f * s;
        atomicMaxFloat(&g_m[dst * HH + hd], s);
    }
    atomicAdd(&g_count[dst], 1);
}

// ---------------- 4) multi-block exclusive scan -> indptr / cursor --------
__global__ void scan1_kernel() {
    __shared__ int sd[1024];
    int b = blockIdx.x, tid = threadIdx.x;
    int i = b * 1024 + tid;
    int v = (i < NN) ? g_count[i] : 0;
    sd[tid] = v;
    __syncthreads();
#pragma unroll
    for (int off = 1; off < 1024; off <<= 1) {
        int t = (tid >= off) ? sd[tid - off] : 0;
        __syncthreads();
        sd[tid] += t;
        __syncthreads();
    }
    if (i < NN) g_indptr[i] = sd[tid] - v;   // local exclusive
    if (tid == 1023) g_btot[b] = sd[1023];
}

__global__ void scan2_kernel(int nb) {
    __shared__ int sd[64];
    int tid = threadIdx.x;
    int v = (tid < nb) ? g_btot[tid] : 0;
    sd[tid] = v;
    __syncthreads();
#pragma unroll
    for (int off = 1; off < 64; off <<= 1) {
        int t = (tid >= off) ? sd[tid - off] : 0;
        __syncthreads();
        sd[tid] += t;
        __syncthreads();
    }
    g_boff[tid] = sd[tid] - v;
    if (tid == nb - 1) g_indptr[NN] = sd[tid];
}

__global__ void scan3_kernel() {
    int i = blockIdx.x * blockDim.x + threadIdx.x;
    if (i < NN) {
        int val = g_indptr[i] + g_boff[i >> 10];
        g_indptr[i] = val;
        g_cursor[i] = val;
    }
}

// ---------------- 5) edge pass 2: exp, denom, CSR scatter ----------------
__global__ void edge_pass2(const int* __restrict__ ei) {
    int e = blockIdx.x * blockDim.x + threadIdx.x;
    if (e >= TOTE) return;
    int src, dst;
    if (e < EE) { src = ei[e]; dst = ei[EE + e]; }
    else        { src = dst = e - EE; }
    float4 s4 = *(const float4*)&g_ssrc[src * HH];
    float4 d4 = *(const float4*)&g_sdst[dst * HH];
    float4 m4 = *(const float4*)&g_m[dst * HH];
    float sc[HH] = { s4.x + d4.x, s4.y + d4.y, s4.z + d4.z, s4.w + d4.w };
    float mv[HH] = { m4.x, m4.y, m4.z, m4.w };
    float ex[HH];
#pragma unroll
    for (int hd = 0; hd < HH; hd++) {
        float s = sc[hd];
        s = (s > 0.f) ? s : 0.2f * s;
        ex[hd] = __expf(s - mv[hd]);
        atomicAdd(&g_denom[dst * HH + hd], ex[hd]);
    }
    int idx = atomicAdd(&g_cursor[dst], 1);
    g_csrc[idx] = src;
    *(float4*)&g_cex[(size_t)idx * 4] = make_float4(ex[0], ex[1], ex[2], ex[3]);
}

// ---------------- 6) CSR gather aggregation + head-mean + bias + ELU -----
__global__ void aggregate_kernel(const float* __restrict__ h,
                                 const float* __restrict__ bias, int view) {
    int dst = blockIdx.x;
    int tid = threadIdx.x;           // 0..127
    int head = tid >> 5;
    float4 acc = make_float4(0.f, 0.f, 0.f, 0.f);
    int beg = g_indptr[dst], end = g_indptr[dst + 1];
    for (int i = beg; i < end; i++) {
        int src = g_csrc[i];
        float ex = g_cex[(size_t)i * 4 + head];
        float4 hv = *(const float4*)&h[(size_t)src * HC + tid * 4];
        acc.x += ex * hv.x;
        acc.y += ex * hv.y;
        acc.z += ex * hv.z;
        acc.w += ex * hv.w;
    }
    float d = g_denom[dst * HH + head];
    float inv = 1.0f / fmaxf(d, 1e-16f);
    __shared__ float s[HC];
    s[tid * 4 + 0] = acc.x * inv;
    s[tid * 4 + 1] = acc.y * inv;
    s[tid * 4 + 2] = acc.z * inv;
    s[tid * 4 + 3] = acc.w * inv;
    __syncthreads();
    float v = 0.25f * (s[tid] + s[tid + 128] + s[tid + 256] + s[tid + 384]) + bias[tid];
    v = (v > 0.f) ? v : expm1f(v);
    g_views[(size_t)view * NN * CC + (size_t)dst * CC + tid] = v;
}

// ---------------- 7) fusion (view attention) + classifier ----------------
__global__ void fusion_kernel(const float* __restrict__ fw,
                              const float* __restrict__ fb,
                              const float* __restrict__ w1,
                              const float* __restrict__ b1,
                              const float* __restrict__ w2,
                              const float* __restrict__ b2,
                              float* __restrict__ out_logits,
                              float* __restrict__ out_w,
                              int npb, int write_w) {
    __shared__ float w1s[CC * 64];
    __shared__ float fws[CC];
    __shared__ float w2s[128];
    __shared__ float red[12];
    __shared__ float sw[3];
    __shared__ float fused_s[CC];
    __shared__ float hcls_s[64];

    int tid = threadIdx.x;           // 128
    for (int i = tid; i < CC * 64; i += 128) w1s[i] = w1[i];
    fws[tid] = fw[tid];
    w2s[tid] = w2[tid];
    __syncthreads();

    const size_t NSTR = (size_t)NN * CC;
    int start = blockIdx.x * npb;
    int endn = min(NN, start + npb);
    int lane = tid & 31, wrp = tid >> 5;

    for (int node = start; node < endn; node++) {
        float v0 = g_views[(size_t)node * CC + tid];
        float v1 = g_views[NSTR + (size_t)node * CC + tid];
        float v2 = g_views[2 * NSTR + (size_t)node * CC + tid];
        float f = fws[tid];
        float p0 = v0 * f, p1 = v1 * f, p2 = v2 * f;
#pragma unroll
        for (int off = 16; off; off >>= 1) {
            p0 += __shfl_xor_sync(0xFFFFFFFFu, p0, off);
            p1 += __shfl_xor_sync(0xFFFFFFFFu, p1, off);
            p2 += __shfl_xor_sync(0xFFFFFFFFu, p2, off);
        }
        if (lane == 0) { red[wrp] = p0; red[4 + wrp] = p1; red[8 + wrp] = p2; }
        __syncthreads();
        if (tid == 0) {
            float s0 = red[0] + red[1] + red[2] + red[3] + fb[0];
            float s1 = red[4] + red[5] + red[6] + red[7] + fb[0];
            float s2 = red[8] + red[9] + red[10] + red[11] + fb[0];
            float mx = fmaxf(s0, fmaxf(s1, s2));
            float e0 = expf(s0 - mx), e1 = expf(s1 - mx), e2 = expf(s2 - mx);
            float inv = 1.0f / (e0 + e1 + e2);
            sw[0] = e0 * inv; sw[1] = e1 * inv; sw[2] = e2 * inv;
            if (write_w) {
                out_w[node * 3 + 0] = sw[0];
                out_w[node * 3 + 1] = sw[1];
                out_w[node * 3 + 2] = sw[2];
            }
        }
        __syncthreads();
        fused_s[tid] = sw[0] * v0 + sw[1] * v1 + sw[2] * v2;
        __syncthreads();
        if (tid < 64) {
            float a = b1[tid];
#pragma unroll 8
            for (int c = 0; c < CC; c++) a += fused_s[c] * w1s[c * 64 + tid];
            hcls_s[tid] = fmaxf(a, 0.f);
        }
        __syncthreads();
        if (tid < 2) {
            float a = b2[tid];
#pragma unroll 8
            for (int k = 0; k < 64; k++) a += hcls_s[k] * w2s[k * 2 + tid];
            out_logits[node * 2 + tid] = a;
        }
        __syncthreads();
    }
}

// ---------------- launcher ----------------
extern "C" void kernel_launch(void* const* d_in, const int* in_sizes, int n_in,
                              void* d_out, int out_size) {
    const float* x     = (const float*)d_in[0];
    const int*   ei0   = (const int*)d_in[1];
    const int*   ei1   = (const int*)d_in[2];
    const int*   ei2   = (const int*)d_in[3];
    const float* W     = (const float*)d_in[4];
    const float* a_src = (const float*)d_in[5];
    const float* a_dst = (const float*)d_in[6];
    const float* b     = (const float*)d_in[7];
    const float* fus_w = (const float*)d_in[8];
    const float* fus_b = (const float*)d_in[9];
    const float* w1    = (const float*)d_in[10];
    const float* b1    = (const float*)d_in[11];
    const float* w2    = (const float*)d_in[12];
    const float* b2    = (const float*)d_in[13];
    float* out = (float*)d_out;

    const int* eis[VV] = { ei0, ei1, ei2 };

    // h pointer for device globals
    float* h_all;
    cudaGetSymbolAddress((void**)&h_all, g_h);

    dim3 gemm_grid(GN / 128, (NN + 127) / 128);
    gemm_tf32_kernel<<<gemm_grid, 256>>>(x, W);

    int sgrid = (NN * 32 + 255) / 256;
    int igrid = (NN * HH + 255) / 256;
    int egrid = (TOTE + 255) / 256;
    int nb = (NN + 1023) / 1024;

    for (int v = 0; v < VV; v++) {
        const float* hv = h_all + (size_t)v * NN * HC;
        s_kernel<<<sgrid, 256>>>(hv, a_src + v * HC, a_dst + v * HC);
        init_kernel<<<igrid, 256>>>();
        edge_pass1<<<egrid, 256>>>(eis[v]);
        scan1_kernel<<<nb, 1024>>>();
        scan2_kernel<<<1, 64>>>(nb);
        scan3_kernel<<<(NN + 255) / 256, 256>>>();
        edge_pass2<<<egrid, 256>>>(eis[v]);
        aggregate_kernel<<<NN, 128>>>(hv, b + v * CC, v);
    }

    int write_w = (out_size >= NN * 2 + NN * 3) ? 1 : 0;
    int nblocks = 500;
    int npb = (NN + nblocks - 1) / nblocks;
    fusion_kernel<<<nblocks, 128>>>(fus_w, fus_b, w1, b1, w2, b2,
                                    out, out + NN * 2, npb, write_w);
}

// round 3
// speedup vs baseline: 3.8129x; 1.5055x over previous
#include <cuda_runtime.h>
#include <cuda_fp16.h>
#include <math.h>
#include <stdint.h>

// ---------------- problem constants ----------------
#define NN      50000
#define EE      800000
#define TOTE    (EE + NN)      // 850000 edges incl self loops
#define FIN     256
#define HH      4
#define CC      128
#define HC      (HH * CC)      // 512
#define VV      3
#define GN      (VV * HC)      // 1536 fused output cols

// ---------------- device scratch (globals; no cudaMalloc allowed) ----------
__device__ __half g_h[(size_t)VV * NN * HC];      // 153.6 MB (all views, fp16)
__device__ float g_views[(size_t)VV * NN * CC];   // 76.8 MB
__device__ float g_ssrc[NN * HH];
__device__ float g_sdst[NN * HH];
__device__ int   g_count[NN];
__device__ int   g_cursor[NN];
__device__ int   g_indptr[NN + 1];
__device__ int   g_btot[64];
__device__ int   g_boff[64];
__device__ int   g_csrc[TOTE];
__device__ float g_cex[(size_t)TOTE * HH];        // 13.6 MB

// ---------------- helpers ----------------
__device__ __forceinline__ uint32_t f2tf(float f) {
    uint32_t u;
    asm("cvt.rna.tf32.f32 %0, %1;" : "=r"(u) : "f"(f));
    return u;
}

__device__ __forceinline__ void mma_tf32(float& c0, float& c1, float& c2, float& c3,
                                         uint32_t a0, uint32_t a1, uint32_t a2, uint32_t a3,
                                         uint32_t b0, uint32_t b1) {
    asm volatile(
        "mma.sync.aligned.m16n8k8.row.col.f32.tf32.tf32.f32 "
        "{%0,%1,%2,%3}, {%4,%5,%6,%7}, {%8,%9}, {%0,%1,%2,%3};"
        : "+f"(c0), "+f"(c1), "+f"(c2), "+f"(c3)
        : "r"(a0), "r"(a1), "r"(a2), "r"(a3), "r"(b0), "r"(b1));
}

// ---------------- 1) TF32 MMA GEMM: g_h = x[N,256] @ W[v][256,512], all views
// BM=128 BN=128 BK=32, 256 threads = 8 warps (2m x 4n), warp tile 64x32
#define AKP 36
#define BNP 136
__global__ void gemm_tf32_kernel(const float* __restrict__ A,
                                 const float* __restrict__ W) {
    __shared__ uint32_t As[128 * AKP];
    __shared__ uint32_t Bs[32 * BNP];

    int tid = threadIdx.x;
    int warp = tid >> 5, lane = tid & 31;
    int wm = warp >> 2;
    int wn = warp & 3;
    int grp = lane >> 2, qid = lane & 3;

    int mbase = blockIdx.y * 128;
    int nbase = blockIdx.x * 128;
    int v = nbase >> 9;
    int nc0 = nbase & 511;
    const float* Bp = W + (size_t)v * FIN * HC + nc0;

    float acc[4][4][4];
#pragma unroll
    for (int mi = 0; mi < 4; mi++)
#pragma unroll
        for (int ni = 0; ni < 4; ni++)
#pragma unroll
            for (int r = 0; r < 4; r++) acc[mi][ni][r] = 0.0f;

    for (int k0 = 0; k0 < FIN; k0 += 32) {
#pragma unroll
        for (int i = 0; i < 4; i++) {
            int idx = tid + i * 256;
            int r = idx >> 3;
            int c4 = (idx & 7) * 4;
            float4 av = make_float4(0.f, 0.f, 0.f, 0.f);
            if (mbase + r < NN)
                av = *(const float4*)&A[(size_t)(mbase + r) * FIN + k0 + c4];
            uint32_t* dst = &As[r * AKP + c4];
            dst[0] = f2tf(av.x); dst[1] = f2tf(av.y);
            dst[2] = f2tf(av.z); dst[3] = f2tf(av.w);
        }
#pragma unroll
        for (int i = 0; i < 4; i++) {
            int idx = tid + i * 256;
            int r = idx >> 5;
            int c4 = (idx & 31) * 4;
            float4 bv = *(const float4*)&Bp[(size_t)(k0 + r) * HC + c4];
            uint32_t* dst = &Bs[r * BNP + c4];
            dst[0] = f2tf(bv.x); dst[1] = f2tf(bv.y);
            dst[2] = f2tf(bv.z); dst[3] = f2tf(bv.w);
        }
        __syncthreads();

#pragma unroll
        for (int kk = 0; kk < 4; kk++) {
            int ko = kk * 8;
            uint32_t af[4][4];
#pragma unroll
            for (int mi = 0; mi < 4; mi++) {
                int rb = wm * 64 + mi * 16;
                af[mi][0] = As[(rb + grp) * AKP + ko + qid];
                af[mi][1] = As[(rb + 8 + grp) * AKP + ko + qid];
                af[mi][2] = As[(rb + grp) * AKP + ko + 4 + qid];
                af[mi][3] = As[(rb + 8 + grp) * AKP + ko + 4 + qid];
            }
            uint32_t bf[4][2];
#pragma unroll
            for (int ni = 0; ni < 4; ni++) {
                int cb = wn * 32 + ni * 8 + grp;
                bf[ni][0] = Bs[(ko + qid) * BNP + cb];
                bf[ni][1] = Bs[(ko + 4 + qid) * BNP + cb];
            }
#pragma unroll
            for (int mi = 0; mi < 4; mi++)
#pragma unroll
                for (int ni = 0; ni < 4; ni++)
                    mma_tf32(acc[mi][ni][0], acc[mi][ni][1], acc[mi][ni][2], acc[mi][ni][3],
                             af[mi][0], af[mi][1], af[mi][2], af[mi][3],
                             bf[ni][0], bf[ni][1]);
        }
        __syncthreads();
    }

    // epilogue -> fp16
    __half* hbase = g_h + (size_t)v * NN * HC;
#pragma unroll
    for (int mi = 0; mi < 4; mi++) {
#pragma unroll
        for (int ni = 0; ni < 4; ni++) {
            int nc = nc0 + wn * 32 + ni * 8 + qid * 2;
            int r0 = mbase + wm * 64 + mi * 16 + grp;
            if (r0 < NN)
                *(__half2*)&hbase[(size_t)r0 * HC + nc] =
                    __floats2half2_rn(acc[mi][ni][0], acc[mi][ni][1]);
            int r1 = r0 + 8;
            if (r1 < NN)
                *(__half2*)&hbase[(size_t)r1 * HC + nc] =
                    __floats2half2_rn(acc[mi][ni][2], acc[mi][ni][3]);
        }
    }
}

// ---------------- 2) attention scalar scores per node (fp16 h) -----------
__global__ void s_kernel(const __half* __restrict__ h,
                         const float* __restrict__ asrc,
                         const float* __restrict__ adst) {
    int gw = (blockIdx.x * blockDim.x + threadIdx.x) >> 5;
    int lane = threadIdx.x & 31;
    if (gw >= NN) return;
    const __half* hr = h + (size_t)gw * HC;
    float ps[HH] = {0.f, 0.f, 0.f, 0.f};
    float pd[HH] = {0.f, 0.f, 0.f, 0.f};
#pragma unroll
    for (int c0 = 0; c0 < HC; c0 += 64) {
        int ch = c0 + lane * 2;
        int hd = ch >> 7;
        float2 vf = __half22float2(*(const __half2*)&hr[ch]);
        ps[hd] += vf.x * asrc[ch] + vf.y * asrc[ch + 1];
        pd[hd] += vf.x * adst[ch] + vf.y * adst[ch + 1];
    }
#pragma unroll
    for (int hd = 0; hd < HH; hd++) {
        float a = ps[hd], d = pd[hd];
#pragma unroll
        for (int off = 16; off; off >>= 1) {
            a += __shfl_xor_sync(0xFFFFFFFFu, a, off);
            d += __shfl_xor_sync(0xFFFFFFFFu, d, off);
        }
        if (lane == 0) {
            g_ssrc[gw * HH + hd] = a;
            g_sdst[gw * HH + hd] = d;
        }
    }
}

// ---------------- per-view init: zero counts ----------------
__global__ void init_kernel() {
    int i = blockIdx.x * blockDim.x + threadIdx.x;
    if (i < NN) g_count[i] = 0;
}

// ---------------- 3) count histogram ----------------
__global__ void count_kernel(const int* __restrict__ ei) {
    int e = blockIdx.x * blockDim.x + threadIdx.x;
    if (e >= TOTE) return;
    int dst = (e < EE) ? ei[EE + e] : (e - EE);
    atomicAdd(&g_count[dst], 1);
}

// ---------------- 4) multi-block exclusive scan -> indptr / cursor --------
__global__ void scan1_kernel() {
    __shared__ int sd[1024];
    int b = blockIdx.x, tid = threadIdx.x;
    int i = b * 1024 + tid;
    int v = (i < NN) ? g_count[i] : 0;
    sd[tid] = v;
    __syncthreads();
#pragma unroll
    for (int off = 1; off < 1024; off <<= 1) {
        int t = (tid >= off) ? sd[tid - off] : 0;
        __syncthreads();
        sd[tid] += t;
        __syncthreads();
    }
    if (i < NN) g_indptr[i] = sd[tid] - v;
    if (tid == 1023) g_btot[b] = sd[1023];
}

__global__ void scan2_kernel(int nb) {
    __shared__ int sd[64];
    int tid = threadIdx.x;
    int v = (tid < nb) ? g_btot[tid] : 0;
    sd[tid] = v;
    __syncthreads();
#pragma unroll
    for (int off = 1; off < 64; off <<= 1) {
        int t = (tid >= off) ? sd[tid - off] : 0;
        __syncthreads();
        sd[tid] += t;
        __syncthreads();
    }
    g_boff[tid] = sd[tid] - v;
    if (tid == nb - 1) g_indptr[NN] = sd[tid];
}

__global__ void scan3_kernel() {
    int i = blockIdx.x * blockDim.x + threadIdx.x;
    if (i < NN) {
        int val = g_indptr[i] + g_boff[i >> 10];
        g_indptr[i] = val;
        g_cursor[i] = val;
    }
}

// ---------------- 5) scatter: scores -> exp -> CSR (no max, no denom) ----
__global__ void scatter_kernel(const int* __restrict__ ei) {
    int e = blockIdx.x * blockDim.x + threadIdx.x;
    if (e >= TOTE) return;
    int src, dst;
    if (e < EE) { src = ei[e]; dst = ei[EE + e]; }
    else        { src = dst = e - EE; }
    float4 s4 = *(const float4*)&g_ssrc[src * HH];
    float4 d4 = *(const float4*)&g_sdst[dst * HH];
    float sc[HH] = { s4.x + d4.x, s4.y + d4.y, s4.z + d4.z, s4.w + d4.w };
    float ex[HH];
#pragma unroll
    for (int hd = 0; hd < HH; hd++) {
        float s = sc[hd];
        s = (s > 0.f) ? s : 0.2f * s;
        ex[hd] = __expf(s);
    }
    int idx = atomicAdd(&g_cursor[dst], 1);
    g_csrc[idx] = src;
    *(float4*)&g_cex[(size_t)idx * 4] = make_float4(ex[0], ex[1], ex[2], ex[3]);
}

// ---------------- 6) CSR gather aggregation (fp16 h) + mean + bias + ELU --
__global__ void aggregate_kernel(const __half* __restrict__ h,
                                 const float* __restrict__ bias, int view) {
    int dst = blockIdx.x;
    int tid = threadIdx.x;           // 0..127
    int head = tid >> 5;
    float a0 = 0.f, a1 = 0.f, a2 = 0.f, a3 = 0.f;
    float dsum = 0.f;
    int beg = g_indptr[dst], end = g_indptr[dst + 1];
    for (int i = beg; i < end; i++) {
        int src = g_csrc[i];
        float ex = g_cex[(size_t)i * 4 + head];
        uint2 u = *(const uint2*)&h[(size_t)src * HC + tid * 4];
        float2 f0 = __half22float2(*(__half2*)&u.x);
        float2 f1 = __half22float2(*(__half2*)&u.y);
        a0 += ex * f0.x;
        a1 += ex * f0.y;
        a2 += ex * f1.x;
        a3 += ex * f1.y;
        dsum += ex;
    }
    float inv = 1.0f / fmaxf(dsum, 1e-16f);
    __shared__ float s[HC];
    s[tid * 4 + 0] = a0 * inv;
    s[tid * 4 + 1] = a1 * inv;
    s[tid * 4 + 2] = a2 * inv;
    s[tid * 4 + 3] = a3 * inv;
    __syncthreads();
    float v = 0.25f * (s[tid] + s[tid + 128] + s[tid + 256] + s[tid + 384]) + bias[tid];
    v = (v > 0.f) ? v : expm1f(v);
    g_views[(size_t)view * NN * CC + (size_t)dst * CC + tid] = v;
}

// ---------------- 7) fusion + classifier: one warp per node --------------
__global__ void fusion_kernel(const float* __restrict__ fw,
                              const float* __restrict__ fb,
                              const float* __restrict__ w1,
                              const float* __restrict__ b1,
                              const float* __restrict__ w2,
                              const float* __restrict__ b2,
                              float* __restrict__ out_logits,
                              float* __restrict__ out_w) {
    __shared__ float w1s[CC * 64];     // 32 KB
    __shared__ float fws[CC];
    __shared__ float w2s[CC];          // [64][2]
    __shared__ float sfused[8][CC];    // per-warp scratch
    __shared__ float sh1[8][64];

    int tid = threadIdx.x;             // 256 = 8 warps
    int warp = tid >> 5, lane = tid & 31;
    for (int i = tid; i < CC * 64; i += 256) w1s[i] = w1[i];
    if (tid < CC) fws[tid] = fw[tid];
    if (tid < CC) w2s[tid] = w2[tid];
    __syncthreads();

    int node = blockIdx.x * 8 + warp;
    if (node >= NN) return;

    const size_t NSTR = (size_t)NN * CC;
    const float* vbase = g_views + (size_t)node * CC;

    float v0[4], v1[4], v2[4];
    float p0 = 0.f, p1 = 0.f, p2 = 0.f;
#pragma unroll
    for (int k = 0; k < 4; k++) {
        int c = lane + 32 * k;
        v0[k] = vbase[c];
        v1[k] = vbase[NSTR + c];
        v2[k] = vbase[2 * NSTR + c];
        float f = fws[c];
        p0 += v0[k] * f;
        p1 += v1[k] * f;
        p2 += v2[k] * f;
    }
#pragma unroll
    for (int off = 16; off; off >>= 1) {
        p0 += __shfl_xor_sync(0xFFFFFFFFu, p0, off);
        p1 += __shfl_xor_sync(0xFFFFFFFFu, p1, off);
        p2 += __shfl_xor_sync(0xFFFFFFFFu, p2, off);
    }
    float fbv = fb[0];
    float s0 = p0 + fbv, s1 = p1 + fbv, s2 = p2 + fbv;
    float mx = fmaxf(s0, fmaxf(s1, s2));
    float e0 = expf(s0 - mx), e1 = expf(s1 - mx), e2 = expf(s2 - mx);
    float inv = 1.0f / (e0 + e1 + e2);
    float w0 = e0 * inv, w1v = e1 * inv, w2v = e2 * inv;
    if (lane == 0) {
        out_w[node * 3 + 0] = w0;
        out_w[node * 3 + 1] = w1v;
        out_w[node * 3 + 2] = w2v;
    }
#pragma unroll
    for (int k = 0; k < 4; k++)
        sfused[warp][lane + 32 * k] = w0 * v0[k] + w1v * v1[k] + w2v * v2[k];
    __syncwarp();

    // layer1: 64 outputs, lane handles j = lane and lane+32
    float acc0 = b1[lane], acc1 = b1[lane + 32];
#pragma unroll 8
    for (int c = 0; c < CC; c++) {
        float fv = sfused[warp][c];
        acc0 += fv * w1s[c * 64 + lane];
        acc1 += fv * w1s[c * 64 + lane + 32];
    }
    sh1[warp][lane] = fmaxf(acc0, 0.f);
    sh1[warp][lane + 32] = fmaxf(acc1, 0.f);
    __syncwarp();

    // layer2: 2 outputs
    float ha = sh1[warp][lane], hb = sh1[warp][lane + 32];
    float q0 = ha * w2s[lane * 2] + hb * w2s[(lane + 32) * 2];
    float q1 = ha * w2s[lane * 2 + 1] + hb * w2s[(lane + 32) * 2 + 1];
#pragma unroll
    for (int off = 16; off; off >>= 1) {
        q0 += __shfl_xor_sync(0xFFFFFFFFu, q0, off);
        q1 += __shfl_xor_sync(0xFFFFFFFFu, q1, off);
    }
    if (lane == 0)
        *(float2*)&out_logits[node * 2] = make_float2(q0 + b2[0], q1 + b2[1]);
}

// ---------------- launcher ----------------
extern "C" void kernel_launch(void* const* d_in, const int* in_sizes, int n_in,
                              void* d_out, int out_size) {
    const float* x     = (const float*)d_in[0];
    const int*   ei0   = (const int*)d_in[1];
    const int*   ei1   = (const int*)d_in[2];
    const int*   ei2   = (const int*)d_in[3];
    const float* W     = (const float*)d_in[4];
    const float* a_src = (const float*)d_in[5];
    const float* a_dst = (const float*)d_in[6];
    const float* b     = (const float*)d_in[7];
    const float* fus_w = (const float*)d_in[8];
    const float* fus_b = (const float*)d_in[9];
    const float* w1    = (const float*)d_in[10];
    const float* b1    = (const float*)d_in[11];
    const float* w2    = (const float*)d_in[12];
    const float* b2    = (const float*)d_in[13];
    float* out = (float*)d_out;

    const int* eis[VV] = { ei0, ei1, ei2 };

    __half* h_all;
    cudaGetSymbolAddress((void**)&h_all, g_h);

    dim3 gemm_grid(GN / 128, (NN + 127) / 128);
    gemm_tf32_kernel<<<gemm_grid, 256>>>(x, W);

    int sgrid = (NN * 32 + 255) / 256;
    int egrid = (TOTE + 255) / 256;
    int nb = (NN + 1023) / 1024;

    for (int v = 0; v < VV; v++) {
        const __half* hv = h_all + (size_t)v * NN * HC;
        s_kernel<<<sgrid, 256>>>(hv, a_src + v * HC, a_dst + v * HC);
        init_kernel<<<(NN + 255) / 256, 256>>>();
        count_kernel<<<egrid, 256>>>(eis[v]);
        scan1_kernel<<<nb, 1024>>>();
        scan2_kernel<<<1, 64>>>(nb);
        scan3_kernel<<<(NN + 255) / 256, 256>>>();
        scatter_kernel<<<egrid, 256>>>(eis[v]);
        aggregate_kernel<<<NN, 128>>>(hv, b + v * CC, v);
    }

    fusion_kernel<<<(NN + 7) / 8, 256>>>(fus_w, fus_b, w1, b1, w2, b2,
                                         out, out + NN * 2);
}

// round 4
// speedup vs baseline: 4.9327x; 1.2937x over previous
#include <cuda_runtime.h>
#include <cuda_fp16.h>
#include <math.h>
#include <stdint.h>

// ---------------- problem constants ----------------
#define NN      50000
#define EE      800000
#define TOTE    (EE + NN)      // 850000 edges incl self loops
#define FIN     256
#define HH      4
#define CC      128
#define HC      (HH * CC)      // 512
#define VV      3
#define GN      (VV * HC)      // 1536 fused output cols

// ---------------- device scratch ----------------
__device__ __half g_h[(size_t)VV * NN * HC];      // 153.6 MB
__device__ float g_views[(size_t)VV * NN * CC];   // 76.8 MB
__device__ float g_ssrc[(size_t)VV * NN * HH];
__device__ float g_sdst[(size_t)VV * NN * HH];
__device__ int   g_count[VV * NN];
__device__ int   g_cursor[VV * NN];
__device__ int   g_indptr[VV * (NN + 1)];
__device__ int   g_btot[VV * 64];
__device__ int   g_boff[VV * 64];
__device__ int   g_csrc[VV * TOTE];
__device__ float g_cex[(size_t)VV * TOTE * HH];   // 40.8 MB

// ---------------- fp16 mma ----------------
__device__ __forceinline__ void mma_f16(float& c0, float& c1, float& c2, float& c3,
                                        uint32_t a0, uint32_t a1, uint32_t a2, uint32_t a3,
                                        uint32_t b0, uint32_t b1) {
    asm volatile(
        "mma.sync.aligned.m16n8k16.row.col.f32.f16.f16.f32 "
        "{%0,%1,%2,%3}, {%4,%5,%6,%7}, {%8,%9}, {%0,%1,%2,%3};"
        : "+f"(c0), "+f"(c1), "+f"(c2), "+f"(c3)
        : "r"(a0), "r"(a1), "r"(a2), "r"(a3), "r"(b0), "r"(b1));
}

// ---------------- 1) fp16 HMMA GEMM + fused s-score epilogue -------------
// h[v] = x[N,256] @ W[v][256,512]; also s_src/s_dst per (node, head).
// BM=128 BN=128 BK=32; 256 thr = 8 warps (2m x 4n); warp tile 64x32.
#define AKP 40   // halfs per As row (conflict-free frag loads)
#define BKP 40   // halfs per Bt row (k-major B)
__global__ void gemm_f16_kernel(const float* __restrict__ A,
                                const float* __restrict__ W,
                                const float* __restrict__ a_src,
                                const float* __restrict__ a_dst) {
    __shared__ __half As[128 * AKP];   // 10.2 KB
    __shared__ __half Bt[128 * BKP];   // 10.2 KB  (Bt[n][k])
    __shared__ float sps[128][4];
    __shared__ float spd[128][4];

    int tid = threadIdx.x;
    int warp = tid >> 5, lane = tid & 31;
    int wm = warp >> 2, wn = warp & 3;
    int grp = lane >> 2, qid = lane & 3;

    int mbase = blockIdx.y * 128;
    int nbase = blockIdx.x * 128;      // 0..1535
    int v = nbase >> 9;
    int nc0 = nbase & 511;
    int head = nc0 >> 7;
    const float* Bp = W + (size_t)v * FIN * HC;

    float acc[4][4][4];
#pragma unroll
    for (int mi = 0; mi < 4; mi++)
#pragma unroll
        for (int ni = 0; ni < 4; ni++)
#pragma unroll
            for (int r = 0; r < 4; r++) acc[mi][ni][r] = 0.0f;

    for (int k0 = 0; k0 < FIN; k0 += 32) {
        // A tile 128x32: float4 loads, fp16 store
#pragma unroll
        for (int i = 0; i < 4; i++) {
            int idx = tid + i * 256;
            int r = idx >> 3;
            int c4 = (idx & 7) * 4;
            float4 av = make_float4(0.f, 0.f, 0.f, 0.f);
            if (mbase + r < NN)
                av = *(const float4*)&A[(size_t)(mbase + r) * FIN + k0 + c4];
            *(__half2*)&As[r * AKP + c4]     = __floats2half2_rn(av.x, av.y);
            *(__half2*)&As[r * AKP + c4 + 2] = __floats2half2_rn(av.z, av.w);
        }
        // B tile 32x128 -> transposed k-major Bt[n][k]
#pragma unroll
        for (int i = 0; i < 4; i++) {
            int idx = tid + i * 256;          // 0..1023
            int col = idx & 127;
            int r4 = (idx >> 7) * 4;
            const float* bp = Bp + (size_t)(k0 + r4) * HC + nc0 + col;
            float b0 = bp[0];
            float b1 = bp[HC];
            float b2 = bp[2 * HC];
            float b3 = bp[3 * HC];
            *(__half2*)&Bt[col * BKP + r4]     = __floats2half2_rn(b0, b1);
            *(__half2*)&Bt[col * BKP + r4 + 2] = __floats2half2_rn(b2, b3);
        }
        __syncthreads();

#pragma unroll
        for (int kk = 0; kk < 2; kk++) {
            int ko = kk * 16;
            uint32_t af[4][4];
#pragma unroll
            for (int mi = 0; mi < 4; mi++) {
                int r0 = wm * 64 + mi * 16 + grp;
                af[mi][0] = *(const uint32_t*)&As[r0 * AKP + ko + qid * 2];
                af[mi][1] = *(const uint32_t*)&As[(r0 + 8) * AKP + ko + qid * 2];
                af[mi][2] = *(const uint32_t*)&As[r0 * AKP + ko + qid * 2 + 8];
                af[mi][3] = *(const uint32_t*)&As[(r0 + 8) * AKP + ko + qid * 2 + 8];
            }
            uint32_t bf[4][2];
#pragma unroll
            for (int ni = 0; ni < 4; ni++) {
                int cb = wn * 32 + ni * 8 + grp;
                bf[ni][0] = *(const uint32_t*)&Bt[cb * BKP + ko + qid * 2];
                bf[ni][1] = *(const uint32_t*)&Bt[cb * BKP + ko + qid * 2 + 8];
            }
#pragma unroll
            for (int mi = 0; mi < 4; mi++)
#pragma unroll
                for (int ni = 0; ni < 4; ni++)
                    mma_f16(acc[mi][ni][0], acc[mi][ni][1], acc[mi][ni][2], acc[mi][ni][3],
                            af[mi][0], af[mi][1], af[mi][2], af[mi][3],
                            bf[ni][0], bf[ni][1]);
        }
        __syncthreads();
    }

    // ---- h store (fp16) ----
    __half* hbase = g_h + (size_t)v * NN * HC;
#pragma unroll
    for (int mi = 0; mi < 4; mi++) {
#pragma unroll
        for (int ni = 0; ni < 4; ni++) {
            int nc = nc0 + wn * 32 + ni * 8 + qid * 2;
            int r0 = mbase + wm * 64 + mi * 16 + grp;
            if (r0 < NN)
                *(__half2*)&hbase[(size_t)r0 * HC + nc] =
                    __floats2half2_rn(acc[mi][ni][0], acc[mi][ni][1]);
            int r1 = r0 + 8;
            if (r1 < NN)
                *(__half2*)&hbase[(size_t)r1 * HC + nc] =
                    __floats2half2_rn(acc[mi][ni][2], acc[mi][ni][3]);
        }
    }

    // ---- fused s-scores: this block covers ONE full head (128 cols) ----
    float as_[4][2], ad_[4][2];
    const float* asv = a_src + v * HC + nc0;
    const float* adv = a_dst + v * HC + nc0;
#pragma unroll
    for (int ni = 0; ni < 4; ni++) {
        int cb = wn * 32 + ni * 8 + qid * 2;
        as_[ni][0] = asv[cb];     as_[ni][1] = asv[cb + 1];
        ad_[ni][0] = adv[cb];     ad_[ni][1] = adv[cb + 1];
    }
#pragma unroll
    for (int mi = 0; mi < 4; mi++) {
        float ps0 = 0.f, pd0 = 0.f, ps1 = 0.f, pd1 = 0.f;
#pragma unroll
        for (int ni = 0; ni < 4; ni++) {
            ps0 += acc[mi][ni][0] * as_[ni][0] + acc[mi][ni][1] * as_[ni][1];
            pd0 += acc[mi][ni][0] * ad_[ni][0] + acc[mi][ni][1] * ad_[ni][1];
            ps1 += acc[mi][ni][2] * as_[ni][0] + acc[mi][ni][3] * as_[ni][1];
            pd1 += acc[mi][ni][2] * ad_[ni][0] + acc[mi][ni][3] * ad_[ni][1];
        }
#pragma unroll
        for (int off = 1; off <= 2; off <<= 1) {
            ps0 += __shfl_xor_sync(0xFFFFFFFFu, ps0, off);
            pd0 += __shfl_xor_sync(0xFFFFFFFFu, pd0, off);
            ps1 += __shfl_xor_sync(0xFFFFFFFFu, ps1, off);
            pd1 += __shfl_xor_sync(0xFFFFFFFFu, pd1, off);
        }
        if (qid == 0) {
            int rl = wm * 64 + mi * 16 + grp;
            sps[rl][wn] = ps0;      spd[rl][wn] = pd0;
            sps[rl + 8][wn] = ps1;  spd[rl + 8][wn] = pd1;
        }
    }
    __syncthreads();
    if (tid < 128) {
        int row = mbase + tid;
        if (row < NN) {
            float s = sps[tid][0] + sps[tid][1] + sps[tid][2] + sps[tid][3];
            float d = spd[tid][0] + spd[tid][1] + spd[tid][2] + spd[tid][3];
            size_t o = ((size_t)v * NN + row) * HH + head;
            g_ssrc[o] = s;
            g_sdst[o] = d;
        }
    }
}

// ---------------- init: zero counts (all views) ----------------
__global__ void init_kernel() {
    int i = blockIdx.x * blockDim.x + threadIdx.x;
    if (i < VV * NN) g_count[i] = 0;
}

// ---------------- count histogram (grid.y = view) ----------------
__global__ void count_kernel(const int* __restrict__ e0,
                             const int* __restrict__ e1,
                             const int* __restrict__ e2) {
    int e = blockIdx.x * blockDim.x + threadIdx.x;
    if (e >= TOTE) return;
    int v = blockIdx.y;
    const int* ei = (v == 0) ? e0 : (v == 1) ? e1 : e2;
    int dst = (e < EE) ? ei[EE + e] : (e - EE);
    atomicAdd(&g_count[v * NN + dst], 1);
}

// ---------------- multi-block scan (grid.y = view) ----------------
__global__ void scan1_kernel() {
    __shared__ int sd[1024];
    int b = blockIdx.x, v = blockIdx.y, tid = threadIdx.x;
    int i = b * 1024 + tid;
    int val = (i < NN) ? g_count[v * NN + i] : 0;
    sd[tid] = val;
    __syncthreads();
#pragma unroll
    for (int off = 1; off < 1024; off <<= 1) {
        int t = (tid >= off) ? sd[tid - off] : 0;
        __syncthreads();
        sd[tid] += t;
        __syncthreads();
    }
    if (i < NN) g_indptr[v * (NN + 1) + i] = sd[tid] - val;
    if (tid == 1023) g_btot[v * 64 + b] = sd[1023];
}

__global__ void scan2_kernel(int nb) {
    __shared__ int sd[64];
    int v = blockIdx.x, tid = threadIdx.x;
    int val = (tid < nb) ? g_btot[v * 64 + tid] : 0;
    sd[tid] = val;
    __syncthreads();
#pragma unroll
    for (int off = 1; off < 64; off <<= 1) {
        int t = (tid >= off) ? sd[tid - off] : 0;
        __syncthreads();
        sd[tid] += t;
        __syncthreads();
    }
    g_boff[v * 64 + tid] = sd[tid] - val;
    if (tid == nb - 1) g_indptr[v * (NN + 1) + NN] = sd[tid];
}

__global__ void scan3_kernel() {
    int i = blockIdx.x * blockDim.x + threadIdx.x;
    int v = blockIdx.y;
    if (i < NN) {
        int val = g_indptr[v * (NN + 1) + i] + g_boff[v * 64 + (i >> 10)];
        g_indptr[v * (NN + 1) + i] = val;
        g_cursor[v * NN + i] = val;
    }
}

// ---------------- scatter: exp(leaky) -> CSR (grid.y = view) -------------
__global__ void scatter_kernel(const int* __restrict__ e0,
                               const int* __restrict__ e1,
                               const int* __restrict__ e2) {
    int e = blockIdx.x * blockDim.x + threadIdx.x;
    if (e >= TOTE) return;
    int v = blockIdx.y;
    const int* ei = (v == 0) ? e0 : (v == 1) ? e1 : e2;
    int src, dst;
    if (e < EE) { src = ei[e]; dst = ei[EE + e]; }
    else        { src = dst = e - EE; }
    float4 s4 = *(const float4*)&g_ssrc[((size_t)v * NN + src) * HH];
    float4 d4 = *(const float4*)&g_sdst[((size_t)v * NN + dst) * HH];
    float sc[HH] = { s4.x + d4.x, s4.y + d4.y, s4.z + d4.z, s4.w + d4.w };
    float ex[HH];
#pragma unroll
    for (int hd = 0; hd < HH; hd++) {
        float s = sc[hd];
        s = (s > 0.f) ? s : 0.2f * s;
        ex[hd] = __expf(s);
    }
    int idx = atomicAdd(&g_cursor[v * NN + dst], 1);
    g_csrc[(size_t)v * TOTE + idx] = src;
    *(float4*)&g_cex[((size_t)v * TOTE + idx) * HH] =
        make_float4(ex[0], ex[1], ex[2], ex[3]);
}

// ---------------- aggregate (grid = NN x VV) ----------------
__global__ void aggregate_kernel(const float* __restrict__ bias_all) {
    int dst = blockIdx.x;
    int v = blockIdx.y;
    int tid = threadIdx.x;           // 0..127
    int head = tid >> 5;
    const __half* h = g_h + (size_t)v * NN * HC;
    const int* csrc = g_csrc + (size_t)v * TOTE;
    const float* cex = g_cex + (size_t)v * TOTE * HH;

    float a0 = 0.f, a1 = 0.f, a2 = 0.f, a3 = 0.f, dsum = 0.f;
    int beg = g_indptr[v * (NN + 1) + dst];
    int end = g_indptr[v * (NN + 1) + dst + 1];
    for (int i = beg; i < end; i++) {
        int src = csrc[i];
        float ex = cex[(size_t)i * HH + head];
        uint2 u = *(const uint2*)&h[(size_t)src * HC + tid * 4];
        float2 f0 = __half22float2(*(__half2*)&u.x);
        float2 f1 = __half22float2(*(__half2*)&u.y);
        a0 += ex * f0.x;
        a1 += ex * f0.y;
        a2 += ex * f1.x;
        a3 += ex * f1.y;
        dsum += ex;
    }
    float inv = 1.0f / fmaxf(dsum, 1e-16f);
    __shared__ float s[HC];
    s[tid * 4 + 0] = a0 * inv;
    s[tid * 4 + 1] = a1 * inv;
    s[tid * 4 + 2] = a2 * inv;
    s[tid * 4 + 3] = a3 * inv;
    __syncthreads();
    float val = 0.25f * (s[tid] + s[tid + 128] + s[tid + 256] + s[tid + 384])
              + bias_all[v * CC + tid];
    val = (val > 0.f) ? val : expm1f(val);
    g_views[(size_t)v * NN * CC + (size_t)dst * CC + tid] = val;
}

// ---------------- fusion + classifier: one warp per node -----------------
__global__ void fusion_kernel(const float* __restrict__ fw,
                              const float* __restrict__ fb,
                              const float* __restrict__ w1,
                              const float* __restrict__ b1,
                              const float* __restrict__ w2,
                              const float* __restrict__ b2,
                              float* __restrict__ out_logits,
                              float* __restrict__ out_w) {
    __shared__ float w1s[CC * 64];
    __shared__ float fws[CC];
    __shared__ float w2s[CC];
    __shared__ float sfused[8][CC];
    __shared__ float sh1[8][64];

    int tid = threadIdx.x;             // 256 = 8 warps
    int warp = tid >> 5, lane = tid & 31;
    for (int i = tid; i < CC * 64; i += 256) w1s[i] = w1[i];
    if (tid < CC) fws[tid] = fw[tid];
    if (tid < CC) w2s[tid] = w2[tid];
    __syncthreads();

    int node = blockIdx.x * 8 + warp;
    if (node >= NN) return;

    const size_t NSTR = (size_t)NN * CC;
    const float* vbase = g_views + (size_t)node * CC;

    float v0[4], v1[4], v2[4];
    float p0 = 0.f, p1 = 0.f, p2 = 0.f;
#pragma unroll
    for (int k = 0; k < 4; k++) {
        int c = lane + 32 * k;
        v0[k] = vbase[c];
        v1[k] = vbase[NSTR + c];
        v2[k] = vbase[2 * NSTR + c];
        float f = fws[c];
        p0 += v0[k] * f;
        p1 += v1[k] * f;
        p2 += v2[k] * f;
    }
#pragma unroll
    for (int off = 16; off; off >>= 1) {
        p0 += __shfl_xor_sync(0xFFFFFFFFu, p0, off);
        p1 += __shfl_xor_sync(0xFFFFFFFFu, p1, off);
        p2 += __shfl_xor_sync(0xFFFFFFFFu, p2, off);
    }
    float fbv = fb[0];
    float s0 = p0 + fbv, s1 = p1 + fbv, s2 = p2 + fbv;
    float mx = fmaxf(s0, fmaxf(s1, s2));
    float e0 = expf(s0 - mx), e1 = expf(s1 - mx), e2 = expf(s2 - mx);
    float inv = 1.0f / (e0 + e1 + e2);
    float w0 = e0 * inv, w1v = e1 * inv, w2v = e2 * inv;
    if (lane == 0) {
        out_w[node * 3 + 0] = w0;
        out_w[node * 3 + 1] = w1v;
        out_w[node * 3 + 2] = w2v;
    }
#pragma unroll
    for (int k = 0; k < 4; k++)
        sfused[warp][lane + 32 * k] = w0 * v0[k] + w1v * v1[k] + w2v * v2[k];
    __syncwarp();

    float acc0 = b1[lane], acc1 = b1[lane + 32];
#pragma unroll 8
    for (int c = 0; c < CC; c++) {
        float fv = sfused[warp][c];
        acc0 += fv * w1s[c * 64 + lane];
        acc1 += fv * w1s[c * 64 + lane + 32];
    }
    sh1[warp][lane] = fmaxf(acc0, 0.f);
    sh1[warp][lane + 32] = fmaxf(acc1, 0.f);
    __syncwarp();

    float ha = sh1[warp][lane], hb = sh1[warp][lane + 32];
    float q0 = ha * w2s[lane * 2] + hb * w2s[(lane + 32) * 2];
    float q1 = ha * w2s[lane * 2 + 1] + hb * w2s[(lane + 32) * 2 + 1];
#pragma unroll
    for (int off = 16; off; off >>= 1) {
        q0 += __shfl_xor_sync(0xFFFFFFFFu, q0, off);
        q1 += __shfl_xor_sync(0xFFFFFFFFu, q1, off);
    }
    if (lane == 0)
        *(float2*)&out_logits[node * 2] = make_float2(q0 + b2[0], q1 + b2[1]);
}

// ---------------- launcher ----------------
extern "C" void kernel_launch(void* const* d_in, const int* in_sizes, int n_in,
                              void* d_out, int out_size) {
    const float* x     = (const float*)d_in[0];
    const int*   ei0   = (const int*)d_in[1];
    const int*   ei1   = (const int*)d_in[2];
    const int*   ei2   = (const int*)d_in[3];
    const float* W     = (const float*)d_in[4];
    const float* a_src = (const float*)d_in[5];
    const float* a_dst = (const float*)d_in[6];
    const float* b     = (const float*)d_in[7];
    const float* fus_w = (const float*)d_in[8];
    const float* fus_b = (const float*)d_in[9];
    const float* w1    = (const float*)d_in[10];
    const float* b1    = (const float*)d_in[11];
    const float* w2    = (const float*)d_in[12];
    const float* b2    = (const float*)d_in[13];
    float* out = (float*)d_out;

    dim3 gemm_grid(GN / 128, (NN + 127) / 128);
    gemm_f16_kernel<<<gemm_grid, 256>>>(x, W, a_src, a_dst);

    int nb = (NN + 1023) / 1024;
    dim3 egrid((TOTE + 255) / 256, VV);

    init_kernel<<<(VV * NN + 255) / 256, 256>>>();
    count_kernel<<<egrid, 256>>>(ei0, ei1, ei2);
    scan1_kernel<<<dim3(nb, VV), 1024>>>();
    scan2_kernel<<<VV, 64>>>(nb);
    scan3_kernel<<<dim3((NN + 255) / 256, VV), 256>>>();
    scatter_kernel<<<egrid, 256>>>(ei0, ei1, ei2);
    aggregate_kernel<<<dim3(NN, VV), 128>>>(b);

    fusion_kernel<<<(NN + 7) / 8, 256>>>(fus_w, fus_b, w1, b1, w2, b2,
                                         out, out + NN * 2);
}